// round 15
// baseline (speedup 1.0000x reference)
#include <cuda_runtime.h>
#include <cuda_bf16.h>
#include <mma.h>
#include <cstdint>
#include <cstddef>

// Problem constants
constexpr int B  = 4;
constexpr int S  = 1024;
constexpr int D  = 1024;
constexpr int H  = 16;
constexpr int DK = 64;
constexpr int M  = B * S;          // 4096

constexpr int LDT = 72;            // smem stride for 64-wide tiles (pad 8) -> 144B rows

// scores scale folded into Q: 0.125 * log2(e)
#define QSCALE 0.18033688011f
#define MASKED_EXP2 (-43.0f)       // 2^-43 ~ exp(-30): negligible, no underflow

// Scratch (device globals; allocation-free per harness rules)
__device__ __align__(16) unsigned short g_qin[(size_t)M * D];   // bf16 inputs
__device__ __align__(16) unsigned short g_kin[(size_t)M * D];
__device__ __align__(16) unsigned short g_vin[(size_t)M * D];
__device__ __align__(16) unsigned short g_wq [(size_t)D * D];   // bf16 weights
__device__ __align__(16) unsigned short g_wk [(size_t)D * D];
__device__ __align__(16) unsigned short g_wv [(size_t)D * D];
__device__ __align__(16) unsigned short g_Qb[(size_t)M * D];    // bf16 projected (Q pre-scaled)
__device__ __align__(16) unsigned short g_Kb[(size_t)M * D];
__device__ __align__(16) unsigned short g_Vb[(size_t)M * D];
__device__ __align__(16) unsigned int g_mbits[(size_t)M * 32];  // packed mask bits
__device__ float d_Xt[(size_t)M * D];
__device__ float d_wmean[D];
__device__ float d_bmean;

// ---------------------------------------------------------------------------
__device__ __forceinline__ uint32_t smem_u32(const void* p) {
    uint32_t a;
    asm("{ .reg .u64 t; cvta.to.shared.u64 t, %1; cvt.u32.u64 %0, t; }" : "=r"(a) : "l"(p));
    return a;
}
#define CP_ASYNC16(dst, src) \
    asm volatile("cp.async.cg.shared.global [%0], [%1], 16;" :: "r"(dst), "l"(src) : "memory")
#define CP_COMMIT()  asm volatile("cp.async.commit_group;" ::: "memory")
#define CP_WAIT(n)   asm volatile("cp.async.wait_group %0;" :: "n"(n) : "memory")

#define LDSM_X4(r0, r1, r2, r3, a) \
    asm volatile("ldmatrix.sync.aligned.m8n8.x4.shared.b16 {%0,%1,%2,%3}, [%4];" \
                 : "=r"(r0), "=r"(r1), "=r"(r2), "=r"(r3) : "r"(a))
#define LDSM_X4_T(r0, r1, r2, r3, a) \
    asm volatile("ldmatrix.sync.aligned.m8n8.x4.trans.shared.b16 {%0,%1,%2,%3}, [%4];" \
                 : "=r"(r0), "=r"(r1), "=r"(r2), "=r"(r3) : "r"(a))
#define MMA16816(d, a0, a1, a2, a3, b0, b1) \
    asm volatile("mma.sync.aligned.m16n8k16.row.col.f32.bf16.bf16.f32 " \
                 "{%0,%1,%2,%3}, {%4,%5,%6,%7}, {%8,%9}, {%0,%1,%2,%3};" \
                 : "+f"((d)[0]), "+f"((d)[1]), "+f"((d)[2]), "+f"((d)[3]) \
                 : "r"(a0), "r"(a1), "r"(a2), "r"(a3), "r"(b0), "r"(b1))

__device__ __forceinline__ uint32_t packbf2(float lo, float hi) {
    __nv_bfloat162 p = __float22bfloat162_rn(make_float2(lo, hi));
    return *(uint32_t*)&p;
}

// ---------------------------------------------------------------------------
// Merged prep: blocks [0,256) convert 6 arrays fp32->bf16;
// [256,768) pack mask bits; [768,800) wmean/bmean.
// ---------------------------------------------------------------------------
__global__ __launch_bounds__(256) void prep_kernel(
    const float* __restrict__ q,  const float* __restrict__ k,  const float* __restrict__ v,
    const float* __restrict__ wq, const float* __restrict__ wk, const float* __restrict__ wv,
    const int* __restrict__ mask, const float* __restrict__ Wo, const float* __restrict__ bo)
{
    __shared__ float sred[256];
    const int bx = blockIdx.x;
    const int t  = threadIdx.x;

    if (bx < 256) {
        // fp32 -> bf16, 6 arrays, grid-stride over 256 blocks
        const float* srcs[6]      = {q, k, v, wq, wk, wv};
        unsigned short* dsts[6]   = {g_qin, g_kin, g_vin, g_wq, g_wk, g_wv};
        const size_t n4s[6] = {(size_t)M * D / 4, (size_t)M * D / 4, (size_t)M * D / 4,
                               (size_t)D * D / 4, (size_t)D * D / 4, (size_t)D * D / 4};
        #pragma unroll 1
        for (int z = 0; z < 6; z++) {
            const float* src = srcs[z];
            unsigned short* dst = dsts[z];
            const size_t n4 = n4s[z];
            for (size_t i = (size_t)bx * 256 + t; i < n4; i += (size_t)256 * 256) {
                float4 f = ((const float4*)src)[i];
                uint2 o;
                o.x = packbf2(f.x, f.y);
                o.y = packbf2(f.z, f.w);
                ((uint2*)dst)[i] = o;
            }
        }
    } else if (bx < 768) {
        // mask pack: 8 rows per block
        const int row  = (bx - 256) * 8 + (t >> 5);
        const int lane = t & 31;
        const int* src = mask + (size_t)row * 1024;
        #pragma unroll
        for (int w = 0; w < 32; w++) {
            int vv = src[w * 32 + lane];
            uint32_t bits = __ballot_sync(0xffffffffu, vv != 0);
            if (lane == 0) g_mbits[(size_t)row * 32 + w] = bits;
        }
    } else {
        // wmean: 32 cols per block
        const int col  = (bx - 768) * 32 + (t & 31);
        const int part = t >> 5;
        float s = 0.0f;
        const int nlo = part * 128, nhi = nlo + 128;
        for (int n = nlo; n < nhi; n++) s += Wo[(size_t)n * D + col];
        sred[t] = s;
        __syncthreads();
        if (part == 0) {
            float tot = 0.0f;
            #pragma unroll
            for (int p = 0; p < 8; p++) tot += sred[p * 32 + (t & 31)];
            d_wmean[col] = tot * (1.0f / D);
        }
        __syncthreads();
        if (bx == 768) {
            float sb = 0.0f;
            #pragma unroll
            for (int i = t; i < D; i += 256) sb += bo[i];
            #pragma unroll
            for (int o = 16; o > 0; o >>= 1) sb += __shfl_xor_sync(0xffffffffu, sb, o);
            if ((t & 31) == 0) sred[t >> 5] = sb;
            __syncthreads();
            if (t == 0) {
                float x = 0.0f;
                #pragma unroll
                for (int p = 0; p < 8; p++) x += sred[p];
                d_bmean = x * (1.0f / D);
            }
        }
    }
}

// ---------------------------------------------------------------------------
// Fused QKV projection, raw mma.sync (verified R14 mapping). Grid (8, 32, 3).
// Q output pre-scaled by QSCALE (softmax scale folded in).
// ---------------------------------------------------------------------------
extern __shared__ char dyn_smem[];

__global__ __launch_bounds__(256, 2) void proj_kernel(
    const float* __restrict__ bq, const float* __restrict__ bk,
    const float* __restrict__ bv)
{
    const uint32_t uS = smem_u32(dyn_smem);
    constexpr uint32_t TILEB  = 128 * LDT * 2;   // 18432
    constexpr uint32_t STAGEB = 2 * TILEB;

    const int t = threadIdx.x, wid = t >> 5, lane = t & 31;
    const int m0 = blockIdx.y * 128, n0 = blockIdx.x * 128;
    const int z  = blockIdx.z;
    const int wm = wid >> 2, wn = wid & 3;
    const int g = lane >> 2, qtid = lane & 3;

    const int x4row = (lane & 7) + ((lane >> 3) & 1) * 8;
    const int x4col = (lane >> 4) * 8;
    const int krow  = lane & 7;
    const int kcol  = (lane >> 3) * 8;

    const unsigned short* Ain; const unsigned short* Wb;
    const float* bias; unsigned short* dst;
    switch (z) {
        case 0: Ain = g_qin; Wb = g_wq; bias = bq; dst = g_Qb; break;
        case 1: Ain = g_kin; Wb = g_wk; bias = bk; dst = g_Kb; break;
        default: Ain = g_vin; Wb = g_wv; bias = bv; dst = g_Vb; break;
    }
    const float osc = (z == 0) ? QSCALE : 1.0f;
    const unsigned short* Asrc = Ain + (size_t)m0 * 1024;
    const unsigned short* Wsrc = Wb  + (size_t)n0 * 1024;

    auto stage = [&](int k0, int buf) {
        const uint32_t uA = uS + buf * STAGEB;
        const uint32_t uB = uA + TILEB;
        #pragma unroll
        for (int i = t; i < 1024; i += 256) {
            int r = i >> 3, q = i & 7;
            CP_ASYNC16(uA + (uint32_t)(r * LDT + q * 8) * 2,
                       Asrc + (size_t)r * 1024 + k0 + q * 8);
        }
        #pragma unroll
        for (int i = t; i < 1024; i += 256) {
            int r = i >> 3, q = i & 7;
            CP_ASYNC16(uB + (uint32_t)(r * LDT + q * 8) * 2,
                       Wsrc + (size_t)r * 1024 + k0 + q * 8);
        }
        CP_COMMIT();
    };

    float acc[4][4][4];
    #pragma unroll
    for (int mb = 0; mb < 4; mb++)
        #pragma unroll
        for (int nt = 0; nt < 4; nt++)
            #pragma unroll
            for (int c = 0; c < 4; c++) acc[mb][nt][c] = 0.0f;

    stage(0, 0);

    for (int k0 = 0; k0 < 1024; k0 += 64) {
        const int buf = (k0 >> 6) & 1;
        if (k0 + 64 < 1024) { stage(k0 + 64, buf ^ 1); CP_WAIT(1); }
        else                { CP_WAIT(0); }
        __syncthreads();

        const uint32_t uA = uS + buf * STAGEB;
        const uint32_t uB = uA + TILEB;

        #pragma unroll
        for (int kc = 0; kc < 2; kc++) {
            uint32_t kb[4][4];
            #pragma unroll
            for (int nt = 0; nt < 4; nt++) {
                uint32_t addr = uB + (uint32_t)((wn * 32 + nt * 8 + krow) * LDT
                                                + kc * 32 + kcol) * 2;
                LDSM_X4(kb[nt][0], kb[nt][1], kb[nt][2], kb[nt][3], addr);
            }
            #pragma unroll
            for (int ks2 = 0; ks2 < 2; ks2++) {
                const int ks = kc * 2 + ks2;
                uint32_t a[4][4];
                #pragma unroll
                for (int mb = 0; mb < 4; mb++) {
                    uint32_t addr = uA + (uint32_t)((wm * 64 + mb * 16 + x4row) * LDT
                                                    + ks * 16 + x4col) * 2;
                    LDSM_X4(a[mb][0], a[mb][1], a[mb][2], a[mb][3], addr);
                }
                #pragma unroll
                for (int mb = 0; mb < 4; mb++)
                    #pragma unroll
                    for (int nt = 0; nt < 4; nt++)
                        MMA16816(acc[mb][nt],
                                 a[mb][0], a[mb][1], a[mb][2], a[mb][3],
                                 kb[nt][2 * ks2], kb[nt][2 * ks2 + 1]);
            }
        }
        __syncthreads();
    }

    float2 bv2[4];
    #pragma unroll
    for (int nt = 0; nt < 4; nt++) {
        int n = n0 + wn * 32 + nt * 8 + qtid * 2;
        bv2[nt] = *(const float2*)&bias[n];
    }
    #pragma unroll
    for (int mb = 0; mb < 4; mb++) {
        const int r0 = m0 + wm * 64 + mb * 16 + g;
        #pragma unroll
        for (int nt = 0; nt < 4; nt++) {
            int n = n0 + wn * 32 + nt * 8 + qtid * 2;
            *(uint32_t*)&dst[(size_t)r0 * 1024 + n] =
                packbf2((acc[mb][nt][0] + bv2[nt].x) * osc,
                        (acc[mb][nt][1] + bv2[nt].y) * osc);
            *(uint32_t*)&dst[(size_t)(r0 + 8) * 1024 + n] =
                packbf2((acc[mb][nt][2] + bv2[nt].x) * osc,
                        (acc[mb][nt][3] + bv2[nt].y) * osc);
        }
    }
}

// ---------------------------------------------------------------------------
// Flash attention v2, 32 q-rows per warp. Grid (4, 64).
// Scores arrive pre-scaled (Q carries QSCALE); p = 2^s, masked -> 2^-43.
// smem: sQ 0..36864 | sK (2 bufs) ..73728 | sV (2 bufs) ..110592
// ---------------------------------------------------------------------------
__global__ __launch_bounds__(256) void flash_kernel()
{
    const uint32_t uQ  = smem_u32(dyn_smem);
    const uint32_t uK0 = uQ + 36864;
    const uint32_t uV0 = uQ + 73728;
    constexpr uint32_t TILEB = 18432;

    const int t = threadIdx.x, wid = t >> 5, lane = t & 31;
    const int mt = blockIdx.x, bh = blockIdx.y;
    const int b = bh >> 4, h = bh & 15;
    const int g = lane >> 2, qtid = lane & 3;
    const int qrow0 = mt * 256;

    const int x4row = (lane & 7) + ((lane >> 3) & 1) * 8;
    const int x4col = (lane >> 4) * 8;
    const int krow  = lane & 7;
    const int kcol  = (lane >> 3) * 8;

    const unsigned short* Ksrc = g_Kb + ((size_t)(b * 1024)) * 1024 + h * 64;
    const unsigned short* Vsrc = g_Vb + ((size_t)(b * 1024)) * 1024 + h * 64;

    auto stage = [&](int kt, int buf) {
        const unsigned short* ks = Ksrc + (size_t)(kt * 128) * 1024;
        const unsigned short* vs = Vsrc + (size_t)(kt * 128) * 1024;
        #pragma unroll
        for (int i = t; i < 1024; i += 256) {
            int r = i >> 3, q = i & 7;
            CP_ASYNC16(uK0 + buf * TILEB + (uint32_t)(r * LDT + q * 8) * 2,
                       ks + (size_t)r * 1024 + q * 8);
        }
        #pragma unroll
        for (int i = t; i < 1024; i += 256) {
            int r = i >> 3, q = i & 7;
            CP_ASYNC16(uV0 + buf * TILEB + (uint32_t)(r * LDT + q * 8) * 2,
                       vs + (size_t)r * 1024 + q * 8);
        }
        CP_COMMIT();
    };

    stage(0, 0);

    const unsigned short* Qsrc = g_Qb + ((size_t)(b * 1024 + qrow0)) * 1024 + h * 64;
    #pragma unroll
    for (int i = t; i < 2048; i += 256) {
        int r = i >> 3, q = i & 7;
        uint4 v = *(const uint4*)(Qsrc + (size_t)r * 1024 + q * 8);
        uint32_t a = uQ + (uint32_t)(r * LDT + q * 8) * 2;
        asm volatile("st.shared.v4.b32 [%0], {%1,%2,%3,%4};"
                     :: "r"(a), "r"(v.x), "r"(v.y), "r"(v.z), "r"(v.w) : "memory");
    }
    __syncthreads();

    uint32_t qa[2][4][4];
    #pragma unroll
    for (int r = 0; r < 2; r++)
        #pragma unroll
        for (int ks = 0; ks < 4; ks++) {
            uint32_t a = uQ + (uint32_t)((wid * 32 + r * 16 + x4row) * LDT + ks * 16 + x4col) * 2;
            LDSM_X4(qa[r][ks][0], qa[r][ks][1], qa[r][ks][2], qa[r][ks][3], a);
        }

    float oacc[2][8][4];
    #pragma unroll
    for (int r = 0; r < 2; r++)
        #pragma unroll
        for (int n = 0; n < 8; n++)
            #pragma unroll
            for (int c = 0; c < 4; c++) oacc[r][n][c] = 0.0f;

    float lsum[2][2] = {{0, 0}, {0, 0}};

    const int rg0 = b * 1024 + qrow0 + wid * 32 + g;
    const uint4* mb = (const uint4*)g_mbits;

    for (int kt = 0; kt < 8; kt++) {
        const int buf = kt & 1;
        if (kt < 7) { stage(kt + 1, buf ^ 1); CP_WAIT(1); }
        else        { CP_WAIT(0); }
        __syncthreads();

        const uint32_t uK = uK0 + buf * TILEB;
        const uint32_t uV = uV0 + buf * TILEB;

        uint4 mw[4];
        mw[0] = mb[(size_t)rg0 * 8 + kt];
        mw[1] = mb[(size_t)(rg0 + 8) * 8 + kt];
        mw[2] = mb[(size_t)(rg0 + 16) * 8 + kt];
        mw[3] = mb[(size_t)(rg0 + 24) * 8 + kt];

        #pragma unroll
        for (int jp = 0; jp < 8; jp++) {
            float s00[4] = {0, 0, 0, 0};
            float s01[4] = {0, 0, 0, 0};
            float s10[4] = {0, 0, 0, 0};
            float s11[4] = {0, 0, 0, 0};

            {
                uint32_t k0, k1, k2, k3;
                uint32_t a0 = uK + (uint32_t)((jp * 16 + krow) * LDT + kcol) * 2;
                LDSM_X4(k0, k1, k2, k3, a0);
                MMA16816(s00, qa[0][0][0], qa[0][0][1], qa[0][0][2], qa[0][0][3], k0, k1);
                MMA16816(s00, qa[0][1][0], qa[0][1][1], qa[0][1][2], qa[0][1][3], k2, k3);
                MMA16816(s01, qa[1][0][0], qa[1][0][1], qa[1][0][2], qa[1][0][3], k0, k1);
                MMA16816(s01, qa[1][1][0], qa[1][1][1], qa[1][1][2], qa[1][1][3], k2, k3);
                uint32_t a1 = uK + (uint32_t)((jp * 16 + krow) * LDT + 32 + kcol) * 2;
                LDSM_X4(k0, k1, k2, k3, a1);
                MMA16816(s00, qa[0][2][0], qa[0][2][1], qa[0][2][2], qa[0][2][3], k0, k1);
                MMA16816(s00, qa[0][3][0], qa[0][3][1], qa[0][3][2], qa[0][3][3], k2, k3);
                MMA16816(s01, qa[1][2][0], qa[1][2][1], qa[1][2][2], qa[1][2][3], k0, k1);
                MMA16816(s01, qa[1][3][0], qa[1][3][1], qa[1][3][2], qa[1][3][3], k2, k3);
                uint32_t a2 = uK + (uint32_t)((jp * 16 + 8 + krow) * LDT + kcol) * 2;
                LDSM_X4(k0, k1, k2, k3, a2);
                MMA16816(s10, qa[0][0][0], qa[0][0][1], qa[0][0][2], qa[0][0][3], k0, k1);
                MMA16816(s10, qa[0][1][0], qa[0][1][1], qa[0][1][2], qa[0][1][3], k2, k3);
                MMA16816(s11, qa[1][0][0], qa[1][0][1], qa[1][0][2], qa[1][0][3], k0, k1);
                MMA16816(s11, qa[1][1][0], qa[1][1][1], qa[1][1][2], qa[1][1][3], k2, k3);
                uint32_t a3 = uK + (uint32_t)((jp * 16 + 8 + krow) * LDT + 32 + kcol) * 2;
                LDSM_X4(k0, k1, k2, k3, a3);
                MMA16816(s10, qa[0][2][0], qa[0][2][1], qa[0][2][2], qa[0][2][3], k0, k1);
                MMA16816(s10, qa[0][3][0], qa[0][3][1], qa[0][3][2], qa[0][3][3], k2, k3);
                MMA16816(s11, qa[1][2][0], qa[1][2][1], qa[1][2][2], qa[1][2][3], k0, k1);
                MMA16816(s11, qa[1][3][0], qa[1][3][1], qa[1][3][2], qa[1][3][3], k2, k3);
            }

            const int sft = (jp & 1) * 16 + qtid * 2;
            uint32_t pa[2][4];

            #pragma unroll
            for (int r = 0; r < 2; r++) {
                uint32_t wA = (&mw[2 * r].x)[jp >> 1];
                uint32_t wB = (&mw[2 * r + 1].x)[jp >> 1];
                float* t0 = (r == 0) ? s00 : s01;
                float* t1 = (r == 0) ? s10 : s11;

                // p = 2^s (s pre-scaled via Q); masked -> 2^-43 (negligible)
                float e00 = exp2f(((wA >> sft)       & 1) ? t0[0] : MASKED_EXP2);
                float e01 = exp2f(((wA >> (sft + 1)) & 1) ? t0[1] : MASKED_EXP2);
                float e02 = exp2f(((wB >> sft)       & 1) ? t0[2] : MASKED_EXP2);
                float e03 = exp2f(((wB >> (sft + 1)) & 1) ? t0[3] : MASKED_EXP2);
                float e10 = exp2f(((wA >> (sft + 8)) & 1) ? t1[0] : MASKED_EXP2);
                float e11 = exp2f(((wA >> (sft + 9)) & 1) ? t1[1] : MASKED_EXP2);
                float e12 = exp2f(((wB >> (sft + 8)) & 1) ? t1[2] : MASKED_EXP2);
                float e13 = exp2f(((wB >> (sft + 9)) & 1) ? t1[3] : MASKED_EXP2);

                lsum[r][0] += e00 + e01 + e10 + e11;
                lsum[r][1] += e02 + e03 + e12 + e13;

                pa[r][0] = packbf2(e00, e01);
                pa[r][1] = packbf2(e02, e03);
                pa[r][2] = packbf2(e10, e11);
                pa[r][3] = packbf2(e12, e13);
            }

            #pragma unroll
            for (int dkp = 0; dkp < 4; dkp++) {
                uint32_t v0, v1, v2, v3;
                uint32_t a = uV + (uint32_t)((jp * 16 + x4row) * LDT + dkp * 16 + x4col) * 2;
                LDSM_X4_T(v0, v1, v2, v3, a);
                MMA16816(oacc[0][2 * dkp],     pa[0][0], pa[0][1], pa[0][2], pa[0][3], v0, v1);
                MMA16816(oacc[0][2 * dkp + 1], pa[0][0], pa[0][1], pa[0][2], pa[0][3], v2, v3);
                MMA16816(oacc[1][2 * dkp],     pa[1][0], pa[1][1], pa[1][2], pa[1][3], v0, v1);
                MMA16816(oacc[1][2 * dkp + 1], pa[1][0], pa[1][1], pa[1][2], pa[1][3], v2, v3);
            }
        }
        __syncthreads();
    }

    #pragma unroll
    for (int r = 0; r < 2; r++)
        #pragma unroll
        for (int o = 1; o < 4; o <<= 1) {
            lsum[r][0] += __shfl_xor_sync(0xffffffffu, lsum[r][0], o);
            lsum[r][1] += __shfl_xor_sync(0xffffffffu, lsum[r][1], o);
        }

    #pragma unroll
    for (int r = 0; r < 2; r++) {
        const float inv0 = 1.0f / lsum[r][0], inv1 = 1.0f / lsum[r][1];
        const size_t row0 = (size_t)rg0 + 16 * r;
        #pragma unroll
        for (int n = 0; n < 8; n++) {
            int col = h * 64 + n * 8 + qtid * 2;
            float v0 = oacc[r][n][0] * inv0, v1 = oacc[r][n][1] * inv0;
            float v2 = oacc[r][n][2] * inv1, v3 = oacc[r][n][3] * inv1;
            v0 = (v0 > 0.2f) ? v0 : 0.0f;
            v1 = (v1 > 0.2f) ? v1 : 0.0f;
            v2 = (v2 > 0.2f) ? v2 : 0.0f;
            v3 = (v3 > 0.2f) ? v3 : 0.0f;
            *(float2*)&d_Xt[row0 * 1024 + col]       = make_float2(v0, v1);
            *(float2*)&d_Xt[(row0 + 8) * 1024 + col] = make_float2(v2, v3);
        }
    }
}

// ---------------------------------------------------------------------------
// Final: out[r,:] = Xt[r,:] + (Xt[r,:] . wmean + bmean)  -- float4 vectorized
// ---------------------------------------------------------------------------
__global__ __launch_bounds__(256) void final_kernel(float* __restrict__ out)
{
    __shared__ float red[8];
    __shared__ float bc;

    const size_t row = blockIdx.x;
    const int t = threadIdx.x;

    float4 x4 = *(const float4*)(d_Xt + row * D + t * 4);
    float4 w4 = *(const float4*)(d_wmean + t * 4);

    float partial = x4.x * w4.x + x4.y * w4.y + x4.z * w4.z + x4.w * w4.w;
    #pragma unroll
    for (int o = 16; o > 0; o >>= 1) partial += __shfl_xor_sync(0xffffffffu, partial, o);
    if ((t & 31) == 0) red[t >> 5] = partial;
    __syncthreads();
    if (t < 8) {
        float s = red[t];
        #pragma unroll
        for (int o = 4; o > 0; o >>= 1) s += __shfl_xor_sync(0xffu, s, o);
        if (t == 0) bc = s + d_bmean;
    }
    __syncthreads();
    const float scalar = bc;

    float4 o4;
    o4.x = x4.x + scalar; o4.y = x4.y + scalar;
    o4.z = x4.z + scalar; o4.w = x4.w + scalar;
    *(float4*)(out + row * D + t * 4) = o4;
}

// ---------------------------------------------------------------------------
extern "C" void kernel_launch(void* const* d_in, const int* in_sizes, int n_in,
                              void* d_out, int out_size)
{
    const float* query = (const float*)d_in[0];
    const float* key_  = (const float*)d_in[1];
    const float* value = (const float*)d_in[2];
    const int*   mask  = (const int*)  d_in[3];
    const float* Wq    = (const float*)d_in[4];
    const float* bq    = (const float*)d_in[5];
    const float* Wk    = (const float*)d_in[6];
    const float* bk    = (const float*)d_in[7];
    const float* Wv    = (const float*)d_in[8];
    const float* bv    = (const float*)d_in[9];
    const float* Wo    = (const float*)d_in[10];
    const float* bo    = (const float*)d_in[11];
    float* out = (float*)d_out;

    constexpr int PROJ_SMEM = 73728;
    constexpr int FA_SMEM   = 110592;
    cudaFuncSetAttribute(proj_kernel,  cudaFuncAttributeMaxDynamicSharedMemorySize, PROJ_SMEM);
    cudaFuncSetAttribute(flash_kernel, cudaFuncAttributeMaxDynamicSharedMemorySize, FA_SMEM);

    prep_kernel<<<800, 256>>>(query, key_, value, Wq, Wk, Wv, mask, Wo, bo);

    proj_kernel<<<dim3(8, 32, 3), 256, PROJ_SMEM>>>(bq, bk, bv);

    flash_kernel<<<dim3(4, 64), 256, FA_SMEM>>>();     // mt x bh

    final_kernel<<<M, 256>>>(out);
}

// round 16
// speedup vs baseline: 1.4833x; 1.4833x over previous
#include <cuda_runtime.h>
#include <cuda_bf16.h>
#include <mma.h>
#include <cstdint>
#include <cstddef>

// Problem constants
constexpr int B  = 4;
constexpr int S  = 1024;
constexpr int D  = 1024;
constexpr int H  = 16;
constexpr int DK = 64;
constexpr int M  = B * S;          // 4096

constexpr int LDT = 72;            // smem stride for 64-wide tiles (pad 8) -> 144B rows

// scores scale folded into Q: 0.125 * log2(e)
#define QSCALE 0.18033688011f
#define MASKED_EXP2 (-43.0f)       // 2^-43 ~ exp(-30): negligible, no underflow

// Scratch (device globals; allocation-free per harness rules)
__device__ __align__(16) unsigned short g_qin[(size_t)M * D];   // bf16 inputs
__device__ __align__(16) unsigned short g_kin[(size_t)M * D];
__device__ __align__(16) unsigned short g_vin[(size_t)M * D];
__device__ __align__(16) unsigned short g_wq [(size_t)D * D];   // bf16 weights
__device__ __align__(16) unsigned short g_wk [(size_t)D * D];
__device__ __align__(16) unsigned short g_wv [(size_t)D * D];
__device__ __align__(16) unsigned short g_Qb[(size_t)M * D];    // bf16 projected (Q pre-scaled)
__device__ __align__(16) unsigned short g_Kb[(size_t)M * D];
__device__ __align__(16) unsigned short g_Vb[(size_t)M * D];
__device__ __align__(16) unsigned int g_mbits[(size_t)M * 32];  // packed mask bits
__device__ float d_Xt[(size_t)M * D];
__device__ float d_wmean[D];
__device__ float d_bmean;

// ---------------------------------------------------------------------------
__device__ __forceinline__ uint32_t smem_u32(const void* p) {
    uint32_t a;
    asm("{ .reg .u64 t; cvta.to.shared.u64 t, %1; cvt.u32.u64 %0, t; }" : "=r"(a) : "l"(p));
    return a;
}
// MUFU EX2 (2^x), same unit __expf uses; NOT libm exp2f (software w/o fast-math)
__device__ __forceinline__ float ex2(float x) {
    float r;
    asm("ex2.approx.ftz.f32 %0, %1;" : "=f"(r) : "f"(x));
    return r;
}
#define CP_ASYNC16(dst, src) \
    asm volatile("cp.async.cg.shared.global [%0], [%1], 16;" :: "r"(dst), "l"(src) : "memory")
#define CP_COMMIT()  asm volatile("cp.async.commit_group;" ::: "memory")
#define CP_WAIT(n)   asm volatile("cp.async.wait_group %0;" :: "n"(n) : "memory")

#define LDSM_X4(r0, r1, r2, r3, a) \
    asm volatile("ldmatrix.sync.aligned.m8n8.x4.shared.b16 {%0,%1,%2,%3}, [%4];" \
                 : "=r"(r0), "=r"(r1), "=r"(r2), "=r"(r3) : "r"(a))
#define LDSM_X4_T(r0, r1, r2, r3, a) \
    asm volatile("ldmatrix.sync.aligned.m8n8.x4.trans.shared.b16 {%0,%1,%2,%3}, [%4];" \
                 : "=r"(r0), "=r"(r1), "=r"(r2), "=r"(r3) : "r"(a))
#define MMA16816(d, a0, a1, a2, a3, b0, b1) \
    asm volatile("mma.sync.aligned.m16n8k16.row.col.f32.bf16.bf16.f32 " \
                 "{%0,%1,%2,%3}, {%4,%5,%6,%7}, {%8,%9}, {%0,%1,%2,%3};" \
                 : "+f"((d)[0]), "+f"((d)[1]), "+f"((d)[2]), "+f"((d)[3]) \
                 : "r"(a0), "r"(a1), "r"(a2), "r"(a3), "r"(b0), "r"(b1))

__device__ __forceinline__ uint32_t packbf2(float lo, float hi) {
    __nv_bfloat162 p = __float22bfloat162_rn(make_float2(lo, hi));
    return *(uint32_t*)&p;
}

// ---------------------------------------------------------------------------
// Merged prep: blocks [0,256) convert 6 arrays fp32->bf16;
// [256,768) pack mask bits; [768,800) wmean/bmean.
// ---------------------------------------------------------------------------
__global__ __launch_bounds__(256) void prep_kernel(
    const float* __restrict__ q,  const float* __restrict__ k,  const float* __restrict__ v,
    const float* __restrict__ wq, const float* __restrict__ wk, const float* __restrict__ wv,
    const int* __restrict__ mask, const float* __restrict__ Wo, const float* __restrict__ bo)
{
    __shared__ float sred[256];
    const int bx = blockIdx.x;
    const int t  = threadIdx.x;

    if (bx < 256) {
        const float* srcs[6]      = {q, k, v, wq, wk, wv};
        unsigned short* dsts[6]   = {g_qin, g_kin, g_vin, g_wq, g_wk, g_wv};
        const size_t n4s[6] = {(size_t)M * D / 4, (size_t)M * D / 4, (size_t)M * D / 4,
                               (size_t)D * D / 4, (size_t)D * D / 4, (size_t)D * D / 4};
        #pragma unroll 1
        for (int z = 0; z < 6; z++) {
            const float* src = srcs[z];
            unsigned short* dst = dsts[z];
            const size_t n4 = n4s[z];
            for (size_t i = (size_t)bx * 256 + t; i < n4; i += (size_t)256 * 256) {
                float4 f = ((const float4*)src)[i];
                uint2 o;
                o.x = packbf2(f.x, f.y);
                o.y = packbf2(f.z, f.w);
                ((uint2*)dst)[i] = o;
            }
        }
    } else if (bx < 768) {
        const int row  = (bx - 256) * 8 + (t >> 5);
        const int lane = t & 31;
        const int* src = mask + (size_t)row * 1024;
        #pragma unroll
        for (int w = 0; w < 32; w++) {
            int vv = src[w * 32 + lane];
            uint32_t bits = __ballot_sync(0xffffffffu, vv != 0);
            if (lane == 0) g_mbits[(size_t)row * 32 + w] = bits;
        }
    } else {
        const int col  = (bx - 768) * 32 + (t & 31);
        const int part = t >> 5;
        float s = 0.0f;
        const int nlo = part * 128, nhi = nlo + 128;
        for (int n = nlo; n < nhi; n++) s += Wo[(size_t)n * D + col];
        sred[t] = s;
        __syncthreads();
        if (part == 0) {
            float tot = 0.0f;
            #pragma unroll
            for (int p = 0; p < 8; p++) tot += sred[p * 32 + (t & 31)];
            d_wmean[col] = tot * (1.0f / D);
        }
        __syncthreads();
        if (bx == 768) {
            float sb = 0.0f;
            #pragma unroll
            for (int i = t; i < D; i += 256) sb += bo[i];
            #pragma unroll
            for (int o = 16; o > 0; o >>= 1) sb += __shfl_xor_sync(0xffffffffu, sb, o);
            if ((t & 31) == 0) sred[t >> 5] = sb;
            __syncthreads();
            if (t == 0) {
                float x = 0.0f;
                #pragma unroll
                for (int p = 0; p < 8; p++) x += sred[p];
                d_bmean = x * (1.0f / D);
            }
        }
    }
}

// ---------------------------------------------------------------------------
// Fused QKV projection, raw mma.sync (verified R14 mapping). Grid (8, 32, 3).
// Q output pre-scaled by QSCALE (softmax scale folded in).
// ---------------------------------------------------------------------------
extern __shared__ char dyn_smem[];

__global__ __launch_bounds__(256, 2) void proj_kernel(
    const float* __restrict__ bq, const float* __restrict__ bk,
    const float* __restrict__ bv)
{
    const uint32_t uS = smem_u32(dyn_smem);
    constexpr uint32_t TILEB  = 128 * LDT * 2;   // 18432
    constexpr uint32_t STAGEB = 2 * TILEB;

    const int t = threadIdx.x, wid = t >> 5, lane = t & 31;
    const int m0 = blockIdx.y * 128, n0 = blockIdx.x * 128;
    const int z  = blockIdx.z;
    const int wm = wid >> 2, wn = wid & 3;
    const int g = lane >> 2, qtid = lane & 3;

    const int x4row = (lane & 7) + ((lane >> 3) & 1) * 8;
    const int x4col = (lane >> 4) * 8;
    const int krow  = lane & 7;
    const int kcol  = (lane >> 3) * 8;

    const unsigned short* Ain; const unsigned short* Wb;
    const float* bias; unsigned short* dst;
    switch (z) {
        case 0: Ain = g_qin; Wb = g_wq; bias = bq; dst = g_Qb; break;
        case 1: Ain = g_kin; Wb = g_wk; bias = bk; dst = g_Kb; break;
        default: Ain = g_vin; Wb = g_wv; bias = bv; dst = g_Vb; break;
    }
    const float osc = (z == 0) ? QSCALE : 1.0f;
    const unsigned short* Asrc = Ain + (size_t)m0 * 1024;
    const unsigned short* Wsrc = Wb  + (size_t)n0 * 1024;

    auto stage = [&](int k0, int buf) {
        const uint32_t uA = uS + buf * STAGEB;
        const uint32_t uB = uA + TILEB;
        #pragma unroll
        for (int i = t; i < 1024; i += 256) {
            int r = i >> 3, q = i & 7;
            CP_ASYNC16(uA + (uint32_t)(r * LDT + q * 8) * 2,
                       Asrc + (size_t)r * 1024 + k0 + q * 8);
        }
        #pragma unroll
        for (int i = t; i < 1024; i += 256) {
            int r = i >> 3, q = i & 7;
            CP_ASYNC16(uB + (uint32_t)(r * LDT + q * 8) * 2,
                       Wsrc + (size_t)r * 1024 + k0 + q * 8);
        }
        CP_COMMIT();
    };

    float acc[4][4][4];
    #pragma unroll
    for (int mb = 0; mb < 4; mb++)
        #pragma unroll
        for (int nt = 0; nt < 4; nt++)
            #pragma unroll
            for (int c = 0; c < 4; c++) acc[mb][nt][c] = 0.0f;

    stage(0, 0);

    for (int k0 = 0; k0 < 1024; k0 += 64) {
        const int buf = (k0 >> 6) & 1;
        if (k0 + 64 < 1024) { stage(k0 + 64, buf ^ 1); CP_WAIT(1); }
        else                { CP_WAIT(0); }
        __syncthreads();

        const uint32_t uA = uS + buf * STAGEB;
        const uint32_t uB = uA + TILEB;

        #pragma unroll
        for (int kc = 0; kc < 2; kc++) {
            uint32_t kb[4][4];
            #pragma unroll
            for (int nt = 0; nt < 4; nt++) {
                uint32_t addr = uB + (uint32_t)((wn * 32 + nt * 8 + krow) * LDT
                                                + kc * 32 + kcol) * 2;
                LDSM_X4(kb[nt][0], kb[nt][1], kb[nt][2], kb[nt][3], addr);
            }
            #pragma unroll
            for (int ks2 = 0; ks2 < 2; ks2++) {
                const int ks = kc * 2 + ks2;
                uint32_t a[4][4];
                #pragma unroll
                for (int mb = 0; mb < 4; mb++) {
                    uint32_t addr = uA + (uint32_t)((wm * 64 + mb * 16 + x4row) * LDT
                                                    + ks * 16 + x4col) * 2;
                    LDSM_X4(a[mb][0], a[mb][1], a[mb][2], a[mb][3], addr);
                }
                #pragma unroll
                for (int mb = 0; mb < 4; mb++)
                    #pragma unroll
                    for (int nt = 0; nt < 4; nt++)
                        MMA16816(acc[mb][nt],
                                 a[mb][0], a[mb][1], a[mb][2], a[mb][3],
                                 kb[nt][2 * ks2], kb[nt][2 * ks2 + 1]);
            }
        }
        __syncthreads();
    }

    float2 bv2[4];
    #pragma unroll
    for (int nt = 0; nt < 4; nt++) {
        int n = n0 + wn * 32 + nt * 8 + qtid * 2;
        bv2[nt] = *(const float2*)&bias[n];
    }
    #pragma unroll
    for (int mb = 0; mb < 4; mb++) {
        const int r0 = m0 + wm * 64 + mb * 16 + g;
        #pragma unroll
        for (int nt = 0; nt < 4; nt++) {
            int n = n0 + wn * 32 + nt * 8 + qtid * 2;
            *(uint32_t*)&dst[(size_t)r0 * 1024 + n] =
                packbf2((acc[mb][nt][0] + bv2[nt].x) * osc,
                        (acc[mb][nt][1] + bv2[nt].y) * osc);
            *(uint32_t*)&dst[(size_t)(r0 + 8) * 1024 + n] =
                packbf2((acc[mb][nt][2] + bv2[nt].x) * osc,
                        (acc[mb][nt][3] + bv2[nt].y) * osc);
        }
    }
}

// ---------------------------------------------------------------------------
// Flash attention v2, 32 q-rows per warp. Grid (4, 64).
// Scores arrive pre-scaled (Q carries QSCALE); p = 2^s via MUFU EX2,
// masked lanes -> 2^-43 (negligible, underflow-free).
// smem: sQ 0..36864 | sK (2 bufs) ..73728 | sV (2 bufs) ..110592
// ---------------------------------------------------------------------------
__global__ __launch_bounds__(256) void flash_kernel()
{
    const uint32_t uQ  = smem_u32(dyn_smem);
    const uint32_t uK0 = uQ + 36864;
    const uint32_t uV0 = uQ + 73728;
    constexpr uint32_t TILEB = 18432;

    const int t = threadIdx.x, wid = t >> 5, lane = t & 31;
    const int mt = blockIdx.x, bh = blockIdx.y;
    const int b = bh >> 4, h = bh & 15;
    const int g = lane >> 2, qtid = lane & 3;
    const int qrow0 = mt * 256;

    const int x4row = (lane & 7) + ((lane >> 3) & 1) * 8;
    const int x4col = (lane >> 4) * 8;
    const int krow  = lane & 7;
    const int kcol  = (lane >> 3) * 8;

    const unsigned short* Ksrc = g_Kb + ((size_t)(b * 1024)) * 1024 + h * 64;
    const unsigned short* Vsrc = g_Vb + ((size_t)(b * 1024)) * 1024 + h * 64;

    auto stage = [&](int kt, int buf) {
        const unsigned short* ks = Ksrc + (size_t)(kt * 128) * 1024;
        const unsigned short* vs = Vsrc + (size_t)(kt * 128) * 1024;
        #pragma unroll
        for (int i = t; i < 1024; i += 256) {
            int r = i >> 3, q = i & 7;
            CP_ASYNC16(uK0 + buf * TILEB + (uint32_t)(r * LDT + q * 8) * 2,
                       ks + (size_t)r * 1024 + q * 8);
        }
        #pragma unroll
        for (int i = t; i < 1024; i += 256) {
            int r = i >> 3, q = i & 7;
            CP_ASYNC16(uV0 + buf * TILEB + (uint32_t)(r * LDT + q * 8) * 2,
                       vs + (size_t)r * 1024 + q * 8);
        }
        CP_COMMIT();
    };

    stage(0, 0);

    const unsigned short* Qsrc = g_Qb + ((size_t)(b * 1024 + qrow0)) * 1024 + h * 64;
    #pragma unroll
    for (int i = t; i < 2048; i += 256) {
        int r = i >> 3, q = i & 7;
        uint4 v = *(const uint4*)(Qsrc + (size_t)r * 1024 + q * 8);
        uint32_t a = uQ + (uint32_t)(r * LDT + q * 8) * 2;
        asm volatile("st.shared.v4.b32 [%0], {%1,%2,%3,%4};"
                     :: "r"(a), "r"(v.x), "r"(v.y), "r"(v.z), "r"(v.w) : "memory");
    }
    __syncthreads();

    uint32_t qa[2][4][4];
    #pragma unroll
    for (int r = 0; r < 2; r++)
        #pragma unroll
        for (int ks = 0; ks < 4; ks++) {
            uint32_t a = uQ + (uint32_t)((wid * 32 + r * 16 + x4row) * LDT + ks * 16 + x4col) * 2;
            LDSM_X4(qa[r][ks][0], qa[r][ks][1], qa[r][ks][2], qa[r][ks][3], a);
        }

    float oacc[2][8][4];
    #pragma unroll
    for (int r = 0; r < 2; r++)
        #pragma unroll
        for (int n = 0; n < 8; n++)
            #pragma unroll
            for (int c = 0; c < 4; c++) oacc[r][n][c] = 0.0f;

    float lsum[2][2] = {{0, 0}, {0, 0}};

    const int rg0 = b * 1024 + qrow0 + wid * 32 + g;
    const uint4* mb = (const uint4*)g_mbits;

    for (int kt = 0; kt < 8; kt++) {
        const int buf = kt & 1;
        if (kt < 7) { stage(kt + 1, buf ^ 1); CP_WAIT(1); }
        else        { CP_WAIT(0); }
        __syncthreads();

        const uint32_t uK = uK0 + buf * TILEB;
        const uint32_t uV = uV0 + buf * TILEB;

        uint4 mw[4];
        mw[0] = mb[(size_t)rg0 * 8 + kt];
        mw[1] = mb[(size_t)(rg0 + 8) * 8 + kt];
        mw[2] = mb[(size_t)(rg0 + 16) * 8 + kt];
        mw[3] = mb[(size_t)(rg0 + 24) * 8 + kt];

        #pragma unroll
        for (int jp = 0; jp < 8; jp++) {
            float s00[4] = {0, 0, 0, 0};
            float s01[4] = {0, 0, 0, 0};
            float s10[4] = {0, 0, 0, 0};
            float s11[4] = {0, 0, 0, 0};

            {
                uint32_t k0, k1, k2, k3;
                uint32_t a0 = uK + (uint32_t)((jp * 16 + krow) * LDT + kcol) * 2;
                LDSM_X4(k0, k1, k2, k3, a0);
                MMA16816(s00, qa[0][0][0], qa[0][0][1], qa[0][0][2], qa[0][0][3], k0, k1);
                MMA16816(s00, qa[0][1][0], qa[0][1][1], qa[0][1][2], qa[0][1][3], k2, k3);
                MMA16816(s01, qa[1][0][0], qa[1][0][1], qa[1][0][2], qa[1][0][3], k0, k1);
                MMA16816(s01, qa[1][1][0], qa[1][1][1], qa[1][1][2], qa[1][1][3], k2, k3);
                uint32_t a1 = uK + (uint32_t)((jp * 16 + krow) * LDT + 32 + kcol) * 2;
                LDSM_X4(k0, k1, k2, k3, a1);
                MMA16816(s00, qa[0][2][0], qa[0][2][1], qa[0][2][2], qa[0][2][3], k0, k1);
                MMA16816(s00, qa[0][3][0], qa[0][3][1], qa[0][3][2], qa[0][3][3], k2, k3);
                MMA16816(s01, qa[1][2][0], qa[1][2][1], qa[1][2][2], qa[1][2][3], k0, k1);
                MMA16816(s01, qa[1][3][0], qa[1][3][1], qa[1][3][2], qa[1][3][3], k2, k3);
                uint32_t a2 = uK + (uint32_t)((jp * 16 + 8 + krow) * LDT + kcol) * 2;
                LDSM_X4(k0, k1, k2, k3, a2);
                MMA16816(s10, qa[0][0][0], qa[0][0][1], qa[0][0][2], qa[0][0][3], k0, k1);
                MMA16816(s10, qa[0][1][0], qa[0][1][1], qa[0][1][2], qa[0][1][3], k2, k3);
                MMA16816(s11, qa[1][0][0], qa[1][0][1], qa[1][0][2], qa[1][0][3], k0, k1);
                MMA16816(s11, qa[1][1][0], qa[1][1][1], qa[1][1][2], qa[1][1][3], k2, k3);
                uint32_t a3 = uK + (uint32_t)((jp * 16 + 8 + krow) * LDT + 32 + kcol) * 2;
                LDSM_X4(k0, k1, k2, k3, a3);
                MMA16816(s10, qa[0][2][0], qa[0][2][1], qa[0][2][2], qa[0][2][3], k0, k1);
                MMA16816(s10, qa[0][3][0], qa[0][3][1], qa[0][3][2], qa[0][3][3], k2, k3);
                MMA16816(s11, qa[1][2][0], qa[1][2][1], qa[1][2][2], qa[1][2][3], k0, k1);
                MMA16816(s11, qa[1][3][0], qa[1][3][1], qa[1][3][2], qa[1][3][3], k2, k3);
            }

            const int sft = (jp & 1) * 16 + qtid * 2;
            uint32_t pa[2][4];

            #pragma unroll
            for (int r = 0; r < 2; r++) {
                uint32_t wA = (&mw[2 * r].x)[jp >> 1];
                uint32_t wB = (&mw[2 * r + 1].x)[jp >> 1];
                float* t0 = (r == 0) ? s00 : s01;
                float* t1 = (r == 0) ? s10 : s11;

                // p = 2^s (s pre-scaled via Q); masked -> 2^-43 (negligible)
                float e00 = ex2(((wA >> sft)       & 1) ? t0[0] : MASKED_EXP2);
                float e01 = ex2(((wA >> (sft + 1)) & 1) ? t0[1] : MASKED_EXP2);
                float e02 = ex2(((wB >> sft)       & 1) ? t0[2] : MASKED_EXP2);
                float e03 = ex2(((wB >> (sft + 1)) & 1) ? t0[3] : MASKED_EXP2);
                float e10 = ex2(((wA >> (sft + 8)) & 1) ? t1[0] : MASKED_EXP2);
                float e11 = ex2(((wA >> (sft + 9)) & 1) ? t1[1] : MASKED_EXP2);
                float e12 = ex2(((wB >> (sft + 8)) & 1) ? t1[2] : MASKED_EXP2);
                float e13 = ex2(((wB >> (sft + 9)) & 1) ? t1[3] : MASKED_EXP2);

                lsum[r][0] += e00 + e01 + e10 + e11;
                lsum[r][1] += e02 + e03 + e12 + e13;

                pa[r][0] = packbf2(e00, e01);
                pa[r][1] = packbf2(e02, e03);
                pa[r][2] = packbf2(e10, e11);
                pa[r][3] = packbf2(e12, e13);
            }

            #pragma unroll
            for (int dkp = 0; dkp < 4; dkp++) {
                uint32_t v0, v1, v2, v3;
                uint32_t a = uV + (uint32_t)((jp * 16 + x4row) * LDT + dkp * 16 + x4col) * 2;
                LDSM_X4_T(v0, v1, v2, v3, a);
                MMA16816(oacc[0][2 * dkp],     pa[0][0], pa[0][1], pa[0][2], pa[0][3], v0, v1);
                MMA16816(oacc[0][2 * dkp + 1], pa[0][0], pa[0][1], pa[0][2], pa[0][3], v2, v3);
                MMA16816(oacc[1][2 * dkp],     pa[1][0], pa[1][1], pa[1][2], pa[1][3], v0, v1);
                MMA16816(oacc[1][2 * dkp + 1], pa[1][0], pa[1][1], pa[1][2], pa[1][3], v2, v3);
            }
        }
        __syncthreads();
    }

    #pragma unroll
    for (int r = 0; r < 2; r++)
        #pragma unroll
        for (int o = 1; o < 4; o <<= 1) {
            lsum[r][0] += __shfl_xor_sync(0xffffffffu, lsum[r][0], o);
            lsum[r][1] += __shfl_xor_sync(0xffffffffu, lsum[r][1], o);
        }

    #pragma unroll
    for (int r = 0; r < 2; r++) {
        const float inv0 = 1.0f / lsum[r][0], inv1 = 1.0f / lsum[r][1];
        const size_t row0 = (size_t)rg0 + 16 * r;
        #pragma unroll
        for (int n = 0; n < 8; n++) {
            int col = h * 64 + n * 8 + qtid * 2;
            float v0 = oacc[r][n][0] * inv0, v1 = oacc[r][n][1] * inv0;
            float v2 = oacc[r][n][2] * inv1, v3 = oacc[r][n][3] * inv1;
            v0 = (v0 > 0.2f) ? v0 : 0.0f;
            v1 = (v1 > 0.2f) ? v1 : 0.0f;
            v2 = (v2 > 0.2f) ? v2 : 0.0f;
            v3 = (v3 > 0.2f) ? v3 : 0.0f;
            *(float2*)&d_Xt[row0 * 1024 + col]       = make_float2(v0, v1);
            *(float2*)&d_Xt[(row0 + 8) * 1024 + col] = make_float2(v2, v3);
        }
    }
}

// ---------------------------------------------------------------------------
// Final: out[r,:] = Xt[r,:] + (Xt[r,:] . wmean + bmean)  -- float4 vectorized
// ---------------------------------------------------------------------------
__global__ __launch_bounds__(256) void final_kernel(float* __restrict__ out)
{
    __shared__ float red[8];
    __shared__ float bc;

    const size_t row = blockIdx.x;
    const int t = threadIdx.x;

    float4 x4 = *(const float4*)(d_Xt + row * D + t * 4);
    float4 w4 = *(const float4*)(d_wmean + t * 4);

    float partial = x4.x * w4.x + x4.y * w4.y + x4.z * w4.z + x4.w * w4.w;
    #pragma unroll
    for (int o = 16; o > 0; o >>= 1) partial += __shfl_xor_sync(0xffffffffu, partial, o);
    if ((t & 31) == 0) red[t >> 5] = partial;
    __syncthreads();
    if (t < 8) {
        float s = red[t];
        #pragma unroll
        for (int o = 4; o > 0; o >>= 1) s += __shfl_xor_sync(0xffu, s, o);
        if (t == 0) bc = s + d_bmean;
    }
    __syncthreads();
    const float scalar = bc;

    float4 o4;
    o4.x = x4.x + scalar; o4.y = x4.y + scalar;
    o4.z = x4.z + scalar; o4.w = x4.w + scalar;
    *(float4*)(out + row * D + t * 4) = o4;
}

// ---------------------------------------------------------------------------
extern "C" void kernel_launch(void* const* d_in, const int* in_sizes, int n_in,
                              void* d_out, int out_size)
{
    const float* query = (const float*)d_in[0];
    const float* key_  = (const float*)d_in[1];
    const float* value = (const float*)d_in[2];
    const int*   mask  = (const int*)  d_in[3];
    const float* Wq    = (const float*)d_in[4];
    const float* bq    = (const float*)d_in[5];
    const float* Wk    = (const float*)d_in[6];
    const float* bk    = (const float*)d_in[7];
    const float* Wv    = (const float*)d_in[8];
    const float* bv    = (const float*)d_in[9];
    const float* Wo    = (const float*)d_in[10];
    const float* bo    = (const float*)d_in[11];
    float* out = (float*)d_out;

    constexpr int PROJ_SMEM = 73728;
    constexpr int FA_SMEM   = 110592;
    cudaFuncSetAttribute(proj_kernel,  cudaFuncAttributeMaxDynamicSharedMemorySize, PROJ_SMEM);
    cudaFuncSetAttribute(flash_kernel, cudaFuncAttributeMaxDynamicSharedMemorySize, FA_SMEM);

    prep_kernel<<<800, 256>>>(query, key_, value, Wq, Wk, Wv, mask, Wo, bo);

    proj_kernel<<<dim3(8, 32, 3), 256, PROJ_SMEM>>>(bq, bk, bv);

    flash_kernel<<<dim3(4, 64), 256, FA_SMEM>>>();     // mt x bh

    final_kernel<<<M, 256>>>(out);
}

// round 17
// speedup vs baseline: 1.6594x; 1.1187x over previous
#include <cuda_runtime.h>
#include <cuda_bf16.h>
#include <mma.h>
#include <cstdint>
#include <cstddef>

// Problem constants
constexpr int B  = 4;
constexpr int S  = 1024;
constexpr int D  = 1024;
constexpr int H  = 16;
constexpr int DK = 64;
constexpr int M  = B * S;          // 4096

constexpr int LDT = 72;            // smem stride for 64-wide tiles (pad 8) -> 144B rows

// scores scale folded into Q: 0.125 * log2(e)
#define QSCALE 0.18033688011f
#define MASKED_EXP2 (-43.0f)       // 2^-43 ~ exp(-30): negligible, no underflow

// Scratch (device globals; allocation-free per harness rules)
__device__ __align__(16) unsigned short g_qin[(size_t)M * D];   // bf16 inputs
__device__ __align__(16) unsigned short g_kin[(size_t)M * D];
__device__ __align__(16) unsigned short g_vin[(size_t)M * D];
__device__ __align__(16) unsigned short g_wq [(size_t)D * D];   // bf16 weights
__device__ __align__(16) unsigned short g_wk [(size_t)D * D];
__device__ __align__(16) unsigned short g_wv [(size_t)D * D];
__device__ __align__(16) unsigned short g_Qb[(size_t)M * D];    // bf16 projected (Q pre-scaled)
__device__ __align__(16) unsigned short g_Kb[(size_t)M * D];
__device__ __align__(16) unsigned short g_Vb[(size_t)M * D];
__device__ __align__(16) unsigned int g_mbits[(size_t)M * 32];  // packed mask bits
__device__ float d_Xt[(size_t)M * D];
__device__ float d_wmean[D];
__device__ float d_bmean;

// ---------------------------------------------------------------------------
__device__ __forceinline__ uint32_t smem_u32(const void* p) {
    uint32_t a;
    asm("{ .reg .u64 t; cvta.to.shared.u64 t, %1; cvt.u32.u64 %0, t; }" : "=r"(a) : "l"(p));
    return a;
}
// MUFU EX2 (2^x), same unit __expf uses; NOT libm exp2f (software w/o fast-math)
__device__ __forceinline__ float ex2(float x) {
    float r;
    asm("ex2.approx.ftz.f32 %0, %1;" : "=f"(r) : "f"(x));
    return r;
}
#define CP_ASYNC16(dst, src) \
    asm volatile("cp.async.cg.shared.global [%0], [%1], 16;" :: "r"(dst), "l"(src) : "memory")
#define CP_COMMIT()  asm volatile("cp.async.commit_group;" ::: "memory")
#define CP_WAIT(n)   asm volatile("cp.async.wait_group %0;" :: "n"(n) : "memory")

#define LDSM_X4(r0, r1, r2, r3, a) \
    asm volatile("ldmatrix.sync.aligned.m8n8.x4.shared.b16 {%0,%1,%2,%3}, [%4];" \
                 : "=r"(r0), "=r"(r1), "=r"(r2), "=r"(r3) : "r"(a))
#define LDSM_X4_T(r0, r1, r2, r3, a) \
    asm volatile("ldmatrix.sync.aligned.m8n8.x4.trans.shared.b16 {%0,%1,%2,%3}, [%4];" \
                 : "=r"(r0), "=r"(r1), "=r"(r2), "=r"(r3) : "r"(a))
#define MMA16816(d, a0, a1, a2, a3, b0, b1) \
    asm volatile("mma.sync.aligned.m16n8k16.row.col.f32.bf16.bf16.f32 " \
                 "{%0,%1,%2,%3}, {%4,%5,%6,%7}, {%8,%9}, {%0,%1,%2,%3};" \
                 : "+f"((d)[0]), "+f"((d)[1]), "+f"((d)[2]), "+f"((d)[3]) \
                 : "r"(a0), "r"(a1), "r"(a2), "r"(a3), "r"(b0), "r"(b1))

__device__ __forceinline__ uint32_t packbf2(float lo, float hi) {
    __nv_bfloat162 p = __float22bfloat162_rn(make_float2(lo, hi));
    return *(uint32_t*)&p;
}

// ---------------------------------------------------------------------------
// Merged prep, fully parallel roles:
//   blocks [0,1536):   fp32->bf16 convert, z = bx>>8 selects array (6 arrays)
//   blocks [1536,2048): pack mask bits (8 rows per block)
//   blocks [2048,2080): wmean/bmean
// ---------------------------------------------------------------------------
__global__ __launch_bounds__(256) void prep_kernel(
    const float* __restrict__ q,  const float* __restrict__ k,  const float* __restrict__ v,
    const float* __restrict__ wq, const float* __restrict__ wk, const float* __restrict__ wv,
    const int* __restrict__ mask, const float* __restrict__ Wo, const float* __restrict__ bo)
{
    __shared__ float sred[256];
    const int bx = blockIdx.x;
    const int t  = threadIdx.x;

    if (bx < 1536) {
        const int z  = bx >> 8;          // 0..5
        const int lb = bx & 255;         // block within array
        const float* src; unsigned short* dst; size_t n4;
        switch (z) {
            case 0: src = q;  dst = g_qin; n4 = (size_t)M * D / 4; break;
            case 1: src = k;  dst = g_kin; n4 = (size_t)M * D / 4; break;
            case 2: src = v;  dst = g_vin; n4 = (size_t)M * D / 4; break;
            case 3: src = wq; dst = g_wq;  n4 = (size_t)D * D / 4; break;
            case 4: src = wk; dst = g_wk;  n4 = (size_t)D * D / 4; break;
            default: src = wv; dst = g_wv; n4 = (size_t)D * D / 4; break;
        }
        for (size_t i = (size_t)lb * 256 + t; i < n4; i += (size_t)256 * 256) {
            float4 f = ((const float4*)src)[i];
            uint2 o;
            o.x = packbf2(f.x, f.y);
            o.y = packbf2(f.z, f.w);
            ((uint2*)dst)[i] = o;
        }
    } else if (bx < 2048) {
        const int row  = (bx - 1536) * 8 + (t >> 5);
        const int lane = t & 31;
        const int* src = mask + (size_t)row * 1024;
        #pragma unroll
        for (int w = 0; w < 32; w++) {
            int vv = src[w * 32 + lane];
            uint32_t bits = __ballot_sync(0xffffffffu, vv != 0);
            if (lane == 0) g_mbits[(size_t)row * 32 + w] = bits;
        }
    } else {
        const int col  = (bx - 2048) * 32 + (t & 31);
        const int part = t >> 5;
        float s = 0.0f;
        const int nlo = part * 128, nhi = nlo + 128;
        for (int n = nlo; n < nhi; n++) s += Wo[(size_t)n * D + col];
        sred[t] = s;
        __syncthreads();
        if (part == 0) {
            float tot = 0.0f;
            #pragma unroll
            for (int p = 0; p < 8; p++) tot += sred[p * 32 + (t & 31)];
            d_wmean[col] = tot * (1.0f / D);
        }
        __syncthreads();
        if (bx == 2048) {
            float sb = 0.0f;
            #pragma unroll
            for (int i = t; i < D; i += 256) sb += bo[i];
            #pragma unroll
            for (int o = 16; o > 0; o >>= 1) sb += __shfl_xor_sync(0xffffffffu, sb, o);
            if ((t & 31) == 0) sred[t >> 5] = sb;
            __syncthreads();
            if (t == 0) {
                float x = 0.0f;
                #pragma unroll
                for (int p = 0; p < 8; p++) x += sred[p];
                d_bmean = x * (1.0f / D);
            }
        }
    }
}

// ---------------------------------------------------------------------------
// Fused QKV projection, raw mma.sync (verified R14 mapping). Grid (8, 32, 3).
// Q output pre-scaled by QSCALE (softmax scale folded in).
// ---------------------------------------------------------------------------
extern __shared__ char dyn_smem[];

__global__ __launch_bounds__(256, 2) void proj_kernel(
    const float* __restrict__ bq, const float* __restrict__ bk,
    const float* __restrict__ bv)
{
    const uint32_t uS = smem_u32(dyn_smem);
    constexpr uint32_t TILEB  = 128 * LDT * 2;   // 18432
    constexpr uint32_t STAGEB = 2 * TILEB;

    const int t = threadIdx.x, wid = t >> 5, lane = t & 31;
    const int m0 = blockIdx.y * 128, n0 = blockIdx.x * 128;
    const int z  = blockIdx.z;
    const int wm = wid >> 2, wn = wid & 3;
    const int g = lane >> 2, qtid = lane & 3;

    const int x4row = (lane & 7) + ((lane >> 3) & 1) * 8;
    const int x4col = (lane >> 4) * 8;
    const int krow  = lane & 7;
    const int kcol  = (lane >> 3) * 8;

    const unsigned short* Ain; const unsigned short* Wb;
    const float* bias; unsigned short* dst;
    switch (z) {
        case 0: Ain = g_qin; Wb = g_wq; bias = bq; dst = g_Qb; break;
        case 1: Ain = g_kin; Wb = g_wk; bias = bk; dst = g_Kb; break;
        default: Ain = g_vin; Wb = g_wv; bias = bv; dst = g_Vb; break;
    }
    const float osc = (z == 0) ? QSCALE : 1.0f;
    const unsigned short* Asrc = Ain + (size_t)m0 * 1024;
    const unsigned short* Wsrc = Wb  + (size_t)n0 * 1024;

    auto stage = [&](int k0, int buf) {
        const uint32_t uA = uS + buf * STAGEB;
        const uint32_t uB = uA + TILEB;
        #pragma unroll
        for (int i = t; i < 1024; i += 256) {
            int r = i >> 3, q = i & 7;
            CP_ASYNC16(uA + (uint32_t)(r * LDT + q * 8) * 2,
                       Asrc + (size_t)r * 1024 + k0 + q * 8);
        }
        #pragma unroll
        for (int i = t; i < 1024; i += 256) {
            int r = i >> 3, q = i & 7;
            CP_ASYNC16(uB + (uint32_t)(r * LDT + q * 8) * 2,
                       Wsrc + (size_t)r * 1024 + k0 + q * 8);
        }
        CP_COMMIT();
    };

    float acc[4][4][4];
    #pragma unroll
    for (int mb = 0; mb < 4; mb++)
        #pragma unroll
        for (int nt = 0; nt < 4; nt++)
            #pragma unroll
            for (int c = 0; c < 4; c++) acc[mb][nt][c] = 0.0f;

    stage(0, 0);

    for (int k0 = 0; k0 < 1024; k0 += 64) {
        const int buf = (k0 >> 6) & 1;
        if (k0 + 64 < 1024) { stage(k0 + 64, buf ^ 1); CP_WAIT(1); }
        else                { CP_WAIT(0); }
        __syncthreads();

        const uint32_t uA = uS + buf * STAGEB;
        const uint32_t uB = uA + TILEB;

        #pragma unroll
        for (int kc = 0; kc < 2; kc++) {
            uint32_t kb[4][4];
            #pragma unroll
            for (int nt = 0; nt < 4; nt++) {
                uint32_t addr = uB + (uint32_t)((wn * 32 + nt * 8 + krow) * LDT
                                                + kc * 32 + kcol) * 2;
                LDSM_X4(kb[nt][0], kb[nt][1], kb[nt][2], kb[nt][3], addr);
            }
            #pragma unroll
            for (int ks2 = 0; ks2 < 2; ks2++) {
                const int ks = kc * 2 + ks2;
                uint32_t a[4][4];
                #pragma unroll
                for (int mb = 0; mb < 4; mb++) {
                    uint32_t addr = uA + (uint32_t)((wm * 64 + mb * 16 + x4row) * LDT
                                                    + ks * 16 + x4col) * 2;
                    LDSM_X4(a[mb][0], a[mb][1], a[mb][2], a[mb][3], addr);
                }
                #pragma unroll
                for (int mb = 0; mb < 4; mb++)
                    #pragma unroll
                    for (int nt = 0; nt < 4; nt++)
                        MMA16816(acc[mb][nt],
                                 a[mb][0], a[mb][1], a[mb][2], a[mb][3],
                                 kb[nt][2 * ks2], kb[nt][2 * ks2 + 1]);
            }
        }
        __syncthreads();
    }

    float2 bv2[4];
    #pragma unroll
    for (int nt = 0; nt < 4; nt++) {
        int n = n0 + wn * 32 + nt * 8 + qtid * 2;
        bv2[nt] = *(const float2*)&bias[n];
    }
    #pragma unroll
    for (int mb = 0; mb < 4; mb++) {
        const int r0 = m0 + wm * 64 + mb * 16 + g;
        #pragma unroll
        for (int nt = 0; nt < 4; nt++) {
            int n = n0 + wn * 32 + nt * 8 + qtid * 2;
            *(uint32_t*)&dst[(size_t)r0 * 1024 + n] =
                packbf2((acc[mb][nt][0] + bv2[nt].x) * osc,
                        (acc[mb][nt][1] + bv2[nt].y) * osc);
            *(uint32_t*)&dst[(size_t)(r0 + 8) * 1024 + n] =
                packbf2((acc[mb][nt][2] + bv2[nt].x) * osc,
                        (acc[mb][nt][3] + bv2[nt].y) * osc);
        }
    }
}

// ---------------------------------------------------------------------------
// Flash attention v2, 32 q-rows per warp. Grid (4, 64).
// Scores arrive pre-scaled (Q carries QSCALE); p = 2^s via MUFU EX2,
// masked lanes -> 2^-43 (negligible, underflow-free).
// smem: sQ 0..36864 | sK (2 bufs) ..73728 | sV (2 bufs) ..110592
// ---------------------------------------------------------------------------
__global__ __launch_bounds__(256) void flash_kernel()
{
    const uint32_t uQ  = smem_u32(dyn_smem);
    const uint32_t uK0 = uQ + 36864;
    const uint32_t uV0 = uQ + 73728;
    constexpr uint32_t TILEB = 18432;

    const int t = threadIdx.x, wid = t >> 5, lane = t & 31;
    const int mt = blockIdx.x, bh = blockIdx.y;
    const int b = bh >> 4, h = bh & 15;
    const int g = lane >> 2, qtid = lane & 3;
    const int qrow0 = mt * 256;

    const int x4row = (lane & 7) + ((lane >> 3) & 1) * 8;
    const int x4col = (lane >> 4) * 8;
    const int krow  = lane & 7;
    const int kcol  = (lane >> 3) * 8;

    const unsigned short* Ksrc = g_Kb + ((size_t)(b * 1024)) * 1024 + h * 64;
    const unsigned short* Vsrc = g_Vb + ((size_t)(b * 1024)) * 1024 + h * 64;

    auto stage = [&](int kt, int buf) {
        const unsigned short* ks = Ksrc + (size_t)(kt * 128) * 1024;
        const unsigned short* vs = Vsrc + (size_t)(kt * 128) * 1024;
        #pragma unroll
        for (int i = t; i < 1024; i += 256) {
            int r = i >> 3, q = i & 7;
            CP_ASYNC16(uK0 + buf * TILEB + (uint32_t)(r * LDT + q * 8) * 2,
                       ks + (size_t)r * 1024 + q * 8);
        }
        #pragma unroll
        for (int i = t; i < 1024; i += 256) {
            int r = i >> 3, q = i & 7;
            CP_ASYNC16(uV0 + buf * TILEB + (uint32_t)(r * LDT + q * 8) * 2,
                       vs + (size_t)r * 1024 + q * 8);
        }
        CP_COMMIT();
    };

    stage(0, 0);

    const unsigned short* Qsrc = g_Qb + ((size_t)(b * 1024 + qrow0)) * 1024 + h * 64;
    #pragma unroll
    for (int i = t; i < 2048; i += 256) {
        int r = i >> 3, q = i & 7;
        uint4 v = *(const uint4*)(Qsrc + (size_t)r * 1024 + q * 8);
        uint32_t a = uQ + (uint32_t)(r * LDT + q * 8) * 2;
        asm volatile("st.shared.v4.b32 [%0], {%1,%2,%3,%4};"
                     :: "r"(a), "r"(v.x), "r"(v.y), "r"(v.z), "r"(v.w) : "memory");
    }
    __syncthreads();

    uint32_t qa[2][4][4];
    #pragma unroll
    for (int r = 0; r < 2; r++)
        #pragma unroll
        for (int ks = 0; ks < 4; ks++) {
            uint32_t a = uQ + (uint32_t)((wid * 32 + r * 16 + x4row) * LDT + ks * 16 + x4col) * 2;
            LDSM_X4(qa[r][ks][0], qa[r][ks][1], qa[r][ks][2], qa[r][ks][3], a);
        }

    float oacc[2][8][4];
    #pragma unroll
    for (int r = 0; r < 2; r++)
        #pragma unroll
        for (int n = 0; n < 8; n++)
            #pragma unroll
            for (int c = 0; c < 4; c++) oacc[r][n][c] = 0.0f;

    float lsum[2][2] = {{0, 0}, {0, 0}};

    const int rg0 = b * 1024 + qrow0 + wid * 32 + g;
    const uint4* mb = (const uint4*)g_mbits;

    for (int kt = 0; kt < 8; kt++) {
        const int buf = kt & 1;
        if (kt < 7) { stage(kt + 1, buf ^ 1); CP_WAIT(1); }
        else        { CP_WAIT(0); }
        __syncthreads();

        const uint32_t uK = uK0 + buf * TILEB;
        const uint32_t uV = uV0 + buf * TILEB;

        uint4 mw[4];
        mw[0] = mb[(size_t)rg0 * 8 + kt];
        mw[1] = mb[(size_t)(rg0 + 8) * 8 + kt];
        mw[2] = mb[(size_t)(rg0 + 16) * 8 + kt];
        mw[3] = mb[(size_t)(rg0 + 24) * 8 + kt];

        #pragma unroll
        for (int jp = 0; jp < 8; jp++) {
            float s00[4] = {0, 0, 0, 0};
            float s01[4] = {0, 0, 0, 0};
            float s10[4] = {0, 0, 0, 0};
            float s11[4] = {0, 0, 0, 0};

            {
                uint32_t k0, k1, k2, k3;
                uint32_t a0 = uK + (uint32_t)((jp * 16 + krow) * LDT + kcol) * 2;
                LDSM_X4(k0, k1, k2, k3, a0);
                MMA16816(s00, qa[0][0][0], qa[0][0][1], qa[0][0][2], qa[0][0][3], k0, k1);
                MMA16816(s00, qa[0][1][0], qa[0][1][1], qa[0][1][2], qa[0][1][3], k2, k3);
                MMA16816(s01, qa[1][0][0], qa[1][0][1], qa[1][0][2], qa[1][0][3], k0, k1);
                MMA16816(s01, qa[1][1][0], qa[1][1][1], qa[1][1][2], qa[1][1][3], k2, k3);
                uint32_t a1 = uK + (uint32_t)((jp * 16 + krow) * LDT + 32 + kcol) * 2;
                LDSM_X4(k0, k1, k2, k3, a1);
                MMA16816(s00, qa[0][2][0], qa[0][2][1], qa[0][2][2], qa[0][2][3], k0, k1);
                MMA16816(s00, qa[0][3][0], qa[0][3][1], qa[0][3][2], qa[0][3][3], k2, k3);
                MMA16816(s01, qa[1][2][0], qa[1][2][1], qa[1][2][2], qa[1][2][3], k0, k1);
                MMA16816(s01, qa[1][3][0], qa[1][3][1], qa[1][3][2], qa[1][3][3], k2, k3);
                uint32_t a2 = uK + (uint32_t)((jp * 16 + 8 + krow) * LDT + kcol) * 2;
                LDSM_X4(k0, k1, k2, k3, a2);
                MMA16816(s10, qa[0][0][0], qa[0][0][1], qa[0][0][2], qa[0][0][3], k0, k1);
                MMA16816(s10, qa[0][1][0], qa[0][1][1], qa[0][1][2], qa[0][1][3], k2, k3);
                MMA16816(s11, qa[1][0][0], qa[1][0][1], qa[1][0][2], qa[1][0][3], k0, k1);
                MMA16816(s11, qa[1][1][0], qa[1][1][1], qa[1][1][2], qa[1][1][3], k2, k3);
                uint32_t a3 = uK + (uint32_t)((jp * 16 + 8 + krow) * LDT + 32 + kcol) * 2;
                LDSM_X4(k0, k1, k2, k3, a3);
                MMA16816(s10, qa[0][2][0], qa[0][2][1], qa[0][2][2], qa[0][2][3], k0, k1);
                MMA16816(s10, qa[0][3][0], qa[0][3][1], qa[0][3][2], qa[0][3][3], k2, k3);
                MMA16816(s11, qa[1][2][0], qa[1][2][1], qa[1][2][2], qa[1][2][3], k0, k1);
                MMA16816(s11, qa[1][3][0], qa[1][3][1], qa[1][3][2], qa[1][3][3], k2, k3);
            }

            const int sft = (jp & 1) * 16 + qtid * 2;
            uint32_t pa[2][4];

            #pragma unroll
            for (int r = 0; r < 2; r++) {
                uint32_t wA = (&mw[2 * r].x)[jp >> 1];
                uint32_t wB = (&mw[2 * r + 1].x)[jp >> 1];
                float* t0 = (r == 0) ? s00 : s01;
                float* t1 = (r == 0) ? s10 : s11;

                // p = 2^s (s pre-scaled via Q); masked -> 2^-43 (negligible)
                float e00 = ex2(((wA >> sft)       & 1) ? t0[0] : MASKED_EXP2);
                float e01 = ex2(((wA >> (sft + 1)) & 1) ? t0[1] : MASKED_EXP2);
                float e02 = ex2(((wB >> sft)       & 1) ? t0[2] : MASKED_EXP2);
                float e03 = ex2(((wB >> (sft + 1)) & 1) ? t0[3] : MASKED_EXP2);
                float e10 = ex2(((wA >> (sft + 8)) & 1) ? t1[0] : MASKED_EXP2);
                float e11 = ex2(((wA >> (sft + 9)) & 1) ? t1[1] : MASKED_EXP2);
                float e12 = ex2(((wB >> (sft + 8)) & 1) ? t1[2] : MASKED_EXP2);
                float e13 = ex2(((wB >> (sft + 9)) & 1) ? t1[3] : MASKED_EXP2);

                lsum[r][0] += e00 + e01 + e10 + e11;
                lsum[r][1] += e02 + e03 + e12 + e13;

                pa[r][0] = packbf2(e00, e01);
                pa[r][1] = packbf2(e02, e03);
                pa[r][2] = packbf2(e10, e11);
                pa[r][3] = packbf2(e12, e13);
            }

            #pragma unroll
            for (int dkp = 0; dkp < 4; dkp++) {
                uint32_t v0, v1, v2, v3;
                uint32_t a = uV + (uint32_t)((jp * 16 + x4row) * LDT + dkp * 16 + x4col) * 2;
                LDSM_X4_T(v0, v1, v2, v3, a);
                MMA16816(oacc[0][2 * dkp],     pa[0][0], pa[0][1], pa[0][2], pa[0][3], v0, v1);
                MMA16816(oacc[0][2 * dkp + 1], pa[0][0], pa[0][1], pa[0][2], pa[0][3], v2, v3);
                MMA16816(oacc[1][2 * dkp],     pa[1][0], pa[1][1], pa[1][2], pa[1][3], v0, v1);
                MMA16816(oacc[1][2 * dkp + 1], pa[1][0], pa[1][1], pa[1][2], pa[1][3], v2, v3);
            }
        }
        __syncthreads();
    }

    #pragma unroll
    for (int r = 0; r < 2; r++)
        #pragma unroll
        for (int o = 1; o < 4; o <<= 1) {
            lsum[r][0] += __shfl_xor_sync(0xffffffffu, lsum[r][0], o);
            lsum[r][1] += __shfl_xor_sync(0xffffffffu, lsum[r][1], o);
        }

    #pragma unroll
    for (int r = 0; r < 2; r++) {
        const float inv0 = 1.0f / lsum[r][0], inv1 = 1.0f / lsum[r][1];
        const size_t row0 = (size_t)rg0 + 16 * r;
        #pragma unroll
        for (int n = 0; n < 8; n++) {
            int col = h * 64 + n * 8 + qtid * 2;
            float v0 = oacc[r][n][0] * inv0, v1 = oacc[r][n][1] * inv0;
            float v2 = oacc[r][n][2] * inv1, v3 = oacc[r][n][3] * inv1;
            v0 = (v0 > 0.2f) ? v0 : 0.0f;
            v1 = (v1 > 0.2f) ? v1 : 0.0f;
            v2 = (v2 > 0.2f) ? v2 : 0.0f;
            v3 = (v3 > 0.2f) ? v3 : 0.0f;
            *(float2*)&d_Xt[row0 * 1024 + col]       = make_float2(v0, v1);
            *(float2*)&d_Xt[(row0 + 8) * 1024 + col] = make_float2(v2, v3);
        }
    }
}

// ---------------------------------------------------------------------------
// Final: out[r,:] = Xt[r,:] + (Xt[r,:] . wmean + bmean)  -- float4 vectorized
// ---------------------------------------------------------------------------
__global__ __launch_bounds__(256) void final_kernel(float* __restrict__ out)
{
    __shared__ float red[8];
    __shared__ float bc;

    const size_t row = blockIdx.x;
    const int t = threadIdx.x;

    float4 x4 = *(const float4*)(d_Xt + row * D + t * 4);
    float4 w4 = *(const float4*)(d_wmean + t * 4);

    float partial = x4.x * w4.x + x4.y * w4.y + x4.z * w4.z + x4.w * w4.w;
    #pragma unroll
    for (int o = 16; o > 0; o >>= 1) partial += __shfl_xor_sync(0xffffffffu, partial, o);
    if ((t & 31) == 0) red[t >> 5] = partial;
    __syncthreads();
    if (t < 8) {
        float s = red[t];
        #pragma unroll
        for (int o = 4; o > 0; o >>= 1) s += __shfl_xor_sync(0xffu, s, o);
        if (t == 0) bc = s + d_bmean;
    }
    __syncthreads();
    const float scalar = bc;

    float4 o4;
    o4.x = x4.x + scalar; o4.y = x4.y + scalar;
    o4.z = x4.z + scalar; o4.w = x4.w + scalar;
    *(float4*)(out + row * D + t * 4) = o4;
}

// ---------------------------------------------------------------------------
extern "C" void kernel_launch(void* const* d_in, const int* in_sizes, int n_in,
                              void* d_out, int out_size)
{
    const float* query = (const float*)d_in[0];
    const float* key_  = (const float*)d_in[1];
    const float* value = (const float*)d_in[2];
    const int*   mask  = (const int*)  d_in[3];
    const float* Wq    = (const float*)d_in[4];
    const float* bq    = (const float*)d_in[5];
    const float* Wk    = (const float*)d_in[6];
    const float* bk    = (const float*)d_in[7];
    const float* Wv    = (const float*)d_in[8];
    const float* bv    = (const float*)d_in[9];
    const float* Wo    = (const float*)d_in[10];
    const float* bo    = (const float*)d_in[11];
    float* out = (float*)d_out;

    constexpr int PROJ_SMEM = 73728;
    constexpr int FA_SMEM   = 110592;
    cudaFuncSetAttribute(proj_kernel,  cudaFuncAttributeMaxDynamicSharedMemorySize, PROJ_SMEM);
    cudaFuncSetAttribute(flash_kernel, cudaFuncAttributeMaxDynamicSharedMemorySize, FA_SMEM);

    prep_kernel<<<2080, 256>>>(query, key_, value, Wq, Wk, Wv, mask, Wo, bo);

    proj_kernel<<<dim3(8, 32, 3), 256, PROJ_SMEM>>>(bq, bk, bv);

    flash_kernel<<<dim3(4, 64), 256, FA_SMEM>>>();     // mt x bh

    final_kernel<<<M, 256>>>(out);
}